// round 14
// baseline (speedup 1.0000x reference)
#include <cuda_runtime.h>
#include <stdint.h>
#include <math.h>

#define NCLS      90
#define KTOP      5000
#define BATCH     16
#define CAND_CAP  131072
#define THRESH    2.2f
#define NBINS     4096
#define EQ_CAP    1024
#define BK_CAP    256
#define BLK_ELEMS 8192
#define NBLOCKS_TOTAL 8672
#define SC_BPI    64      // scatter blocks per image

typedef unsigned long long u64;

// ---------------- scratch (module-static device globals; no allocs) ----------------
__device__ uint2  g_cand[BATCH][CAND_CAP];
__device__ int    g_cand_cnt[BATCH];               // reset by eq_kernel
__device__ int    g_hist[BATCH][NBINS];            // filled by collect; reset by bstar
__device__ int    g_bstar[BATCH];
__device__ int    g_krem[BATCH];
__device__ u64    g_eq[BATCH][EQ_CAP];
__device__ int    g_eq_cnt[BATCH];                 // reset by eq_kernel
__device__ int    g_bk_cnt[BATCH][NCLS];           // reset by warp_nms
__device__ float4 g_bk_nb  [BATCH][NCLS][BK_CAP];
__device__ float  g_bk_area[BATCH][NCLS][BK_CAP];
__device__ u64    g_bk_key [BATCH][NCLS][BK_CAP];
__device__ float  g_bk_out6[BATCH][NCLS][BK_CAP][6];
__device__ int    g_surv_cnt[BATCH];               // reset by merge
__device__ u64    g_surv_key[BATCH][KTOP];
__device__ int    g_surv_ref[BATCH][KTOP];         // cls*BK_CAP + pos

__device__ __forceinline__ unsigned val2key(float v) {
    unsigned ub = __float_as_uint(v);
    return (ub & 0x80000000u) ? ~ub : (ub | 0x80000000u);
}
__device__ __forceinline__ float key2val(unsigned u) {
    unsigned bits = (u & 0x80000000u) ? (u & 0x7FFFFFFFu) : ~u;
    return __uint_as_float(bits);
}
__device__ __forceinline__ int val2bin(float v) {
    int bin = (int)((v - THRESH) * 1024.0f);
    return min(max(bin, 0), NBINS - 1);
}

// decode one candidate and push into its (image,class) bucket
__device__ __forceinline__ void decode_push(
    int b, unsigned keybits, unsigned flat,
    const float* __restrict__ bx0, const float* __restrict__ bx1,
    const float* __restrict__ bx2, const float* __restrict__ bx3,
    const float* __restrict__ bx4, const float* __restrict__ anchors)
{
    float v   = key2val(keybits);
    int cls   = (int)(flat % NCLS);
    int aIdx  = (int)(flat / NCLS);
    int off, W; const float* bp;
    if (aIdx < 36864)      { off = 0;     W = 64; bp = bx0; }
    else if (aIdx < 46080) { off = 36864; W = 32; bp = bx1; }
    else if (aIdx < 48384) { off = 46080; W = 16; bp = bx2; }
    else if (aIdx < 48960) { off = 48384; W = 8;  bp = bx3; }
    else                   { off = 48960; W = 4;  bp = bx4; }
    int rel  = aIdx - off;
    int a    = rel % 9, cell = rel / 9;
    int h    = cell / W, w = cell - h * W;
    int HW   = W * W;
    const float* bb = bp + ((size_t)b * 36 + (size_t)a * 4) * HW + h * W + w;
    float ty = bb[0], tx = bb[HW], th = bb[2 * HW], tw = bb[3 * HW];
    float a0 = anchors[aIdx * 4 + 0], a1 = anchors[aIdx * 4 + 1];
    float a2 = anchors[aIdx * 4 + 2], a3 = anchors[aIdx * 4 + 3];
    float ya = (a0 + a2) * 0.5f, xa = (a1 + a3) * 0.5f;
    float ha = a2 - a0, wa = a3 - a1;
    float hh = expf(th) * ha, ww2 = expf(tw) * wa;
    float yc = ty * ha + ya, xc = tx * wa + xa;
    float b0 = yc - hh * 0.5f, b1 = xc - ww2 * 0.5f;
    float b2 = yc + hh * 0.5f, b3 = xc + ww2 * 0.5f;
    float co = (float)cls * 10000.0f;
    float4 nb = make_float4(b0 + co, b1 + co, b2 + co, b3 + co);
    float ar  = (nb.z - nb.x) * (nb.w - nb.y);
    u64 key   = ((u64)keybits << 32) | (u64)(0xFFFFFFFFu - flat);
    float score = 1.0f / (1.0f + expf(-v));
    int p = atomicAdd(&g_bk_cnt[b][cls], 1);
    if (p < BK_CAP) {
        g_bk_nb[b][cls][p]   = nb;
        g_bk_area[b][cls][p] = ar;
        g_bk_key[b][cls][p]  = key;
        g_bk_out6[b][cls][p][0] = b0; g_bk_out6[b][cls][p][1] = b1;
        g_bk_out6[b][cls][p][2] = b2; g_bk_out6[b][cls][p][3] = b3;
        g_bk_out6[b][cls][p][4] = score;
        g_bk_out6[b][cls][p][5] = (float)(cls + 1);
    }
}

// ---------------- kernel 1: fused threshold-collect + histogram ---------------------
__global__ void __launch_bounds__(256) collect_fused_kernel(
    const float* __restrict__ c0, const float* __restrict__ c1,
    const float* __restrict__ c2, const float* __restrict__ c3,
    const float* __restrict__ c4)
{
    int bid = blockIdx.x;
    int lw, perImg, bpI, anchorOff, blk; const float* cp;
    if      (bid < 6480) { lw = 6; perImg = 3317760; bpI = 405; anchorOff = 0;     cp = c0; blk = bid; }
    else if (bid < 8112) { lw = 5; perImg = 829440;  bpI = 102; anchorOff = 36864; cp = c1; blk = bid - 6480; }
    else if (bid < 8528) { lw = 4; perImg = 207360;  bpI = 26;  anchorOff = 46080; cp = c2; blk = bid - 8112; }
    else if (bid < 8640) { lw = 3; perImg = 51840;   bpI = 7;   anchorOff = 48384; cp = c3; blk = bid - 8528; }
    else                 { lw = 2; perImg = 12960;   bpI = 2;   anchorOff = 48960; cp = c4; blk = bid - 8640; }

    int b     = blk / bpI;
    int chunk = blk - b * bpI;
    int base  = chunk * BLK_ELEMS + threadIdx.x * 4;

    __shared__ uint2 sc[512];
    __shared__ int scnt;
    __shared__ int sbase;
    if (threadIdx.x == 0) scnt = 0;
    __syncthreads();

    const float* img = cp + (size_t)b * perImg;

    float4 v[8];
    bool fullc = (chunk * BLK_ELEMS + BLK_ELEMS) <= perImg;
    if (fullc) {
        #pragma unroll
        for (int u = 0; u < 8; u++)
            v[u] = __ldcs(reinterpret_cast<const float4*>(img + base + u * 1024));
    } else {
        #pragma unroll
        for (int u = 0; u < 8; u++) {
            int g = base + u * 1024;
            if (g < perImg) v[u] = __ldcs(reinterpret_cast<const float4*>(img + g));
            else            v[u] = make_float4(-10.f, -10.f, -10.f, -10.f);
        }
    }

    unsigned hm = 0u;
    #pragma unroll
    for (int u = 0; u < 8; u++) {
        if (v[u].x > THRESH) hm |= (1u << (4 * u + 0));
        if (v[u].y > THRESH) hm |= (1u << (4 * u + 1));
        if (v[u].z > THRESH) hm |= (1u << (4 * u + 2));
        if (v[u].w > THRESH) hm |= (1u << (4 * u + 3));
    }

    int W = 1 << lw;
    while (hm) {
        int e = __ffs(hm) - 1;
        hm &= hm - 1;
        int gidx = base + ((e >> 2) << 10) + (e & 3);
        float val = __ldg(img + gidx);
        int w  = gidx & (W - 1);
        int t  = gidx >> lw;
        int h  = t & (W - 1);
        int ch = t >> lw;
        int a  = ch / NCLS;
        int c  = ch - a * NCLS;
        unsigned flat = (unsigned)((anchorOff + ((h << lw) + w) * 9 + a) * NCLS + c);
        atomicAdd(&g_hist[b][val2bin(val)], 1);        // fused histogram (spread bins)
        int p = atomicAdd(&scnt, 1);
        if (p < 512) sc[p] = make_uint2(val2key(val), flat);
    }
    __syncthreads();
    int cnt = min(scnt, 512);
    if (threadIdx.x == 0) sbase = atomicAdd(&g_cand_cnt[b], cnt);
    __syncthreads();
    if (threadIdx.x < cnt) {
        int p = sbase + threadIdx.x;
        if (p < CAND_CAP) g_cand[b][p] = sc[threadIdx.x];
    }
    for (int i = 256 + threadIdx.x; i < cnt; i += 256) {
        int p = sbase + i;
        if (p < CAND_CAP) g_cand[b][p] = sc[i];
    }
}

// ---------------- kernel 2: suffix-scan -> (bstar,krem); re-zero hist ---------------
__global__ void __launch_bounds__(1024) bstar_kernel()
{
    __shared__ int sA[NBINS];
    __shared__ int sB[NBINS];
    int b = blockIdx.x, tid = threadIdx.x;
    int n = min(g_cand_cnt[b], CAND_CAP);
    for (int i = tid; i < NBINS; i += 1024) {
        sA[i] = g_hist[b][i];
        g_hist[b][i] = 0;                       // reset for next replay
    }
    __syncthreads();
    int* src = sA; int* dst = sB;
    for (int off = 1; off < NBINS; off <<= 1) {
        for (int i = tid; i < NBINS; i += 1024)
            dst[i] = src[i] + ((i + off < NBINS) ? src[i + off] : 0);
        __syncthreads();
        int* tm = src; src = dst; dst = tm;
    }
    int K = (KTOP < n) ? KTOP : n;
    for (int i = tid; i < NBINS; i += 1024) {
        int inc = src[i];
        int exc = (i + 1 < NBINS) ? src[i + 1] : 0;
        if (inc >= K && exc < K) { g_bstar[b] = i; g_krem[b] = K - exc; }
    }
}

// ---------------- kernel 3: scatter + inline decode into class buckets --------------
__global__ void __launch_bounds__(256) scatter_kernel(
    const float* __restrict__ bx0, const float* __restrict__ bx1,
    const float* __restrict__ bx2, const float* __restrict__ bx3,
    const float* __restrict__ bx4, const float* __restrict__ anchors)
{
    int b   = blockIdx.x / SC_BPI;
    int sl  = blockIdx.x - b * SC_BPI;
    int n   = min(g_cand_cnt[b], CAND_CAP);
    int per = (n + SC_BPI - 1) / SC_BPI;
    int lo  = sl * per, hi = min(lo + per, n);
    int bstar = g_bstar[b];
    for (int i = lo + threadIdx.x; i < hi; i += 256) {
        uint2 e = g_cand[b][i];
        float v = key2val(e.x);
        int bin = val2bin(v);
        if (bin > bstar) {
            decode_push(b, e.x, e.y, bx0, bx1, bx2, bx3, bx4, anchors);
        } else if (bin == bstar) {
            int p = atomicAdd(&g_eq_cnt[b], 1);
            if (p < EQ_CAP)
                g_eq[b][p] = ((u64)e.x << 32) | (u64)(0xFFFFFFFFu - e.y);
        }
    }
}

// ---------------- kernel 4: boundary bin: sort, take exactly krem, decode -----------
__global__ void __launch_bounds__(256) eq_kernel(
    const float* __restrict__ bx0, const float* __restrict__ bx1,
    const float* __restrict__ bx2, const float* __restrict__ bx3,
    const float* __restrict__ bx4, const float* __restrict__ anchors)
{
    __shared__ u64 eqS[EQ_CAP];
    int b = blockIdx.x, tid = threadIdx.x;
    int eq = min(g_eq_cnt[b], EQ_CAP);
    int krem = g_krem[b];
    int P = 1; while (P < eq) P <<= 1;
    if (P < 1) P = 1;
    for (int i = tid; i < P; i += 256) eqS[i] = (i < eq) ? g_eq[b][i] : 0ull;
    __syncthreads();
    for (int ksz = 2; ksz <= P; ksz <<= 1) {
        for (int j = ksz >> 1; j > 0; j >>= 1) {
            for (int i = tid; i < P; i += 256) {
                int ixj = i ^ j;
                if (ixj > i) {
                    u64 a = eqS[i], c = eqS[ixj];
                    bool descSeg = ((i & ksz) == 0);
                    if (descSeg ? (a < c) : (a > c)) { eqS[i] = c; eqS[ixj] = a; }
                }
            }
            __syncthreads();
        }
    }
    if (krem > eq) krem = eq;
    for (int i = tid; i < krem; i += 256) {
        u64 a = eqS[i];
        decode_push(b, (unsigned)(a >> 32), 0xFFFFFFFFu - (unsigned)(a & 0xFFFFFFFFull),
                    bx0, bx1, bx2, bx3, bx4, anchors);
    }
    if (tid == 0) { g_eq_cnt[b] = 0; g_cand_cnt[b] = 0; }
}

// ---------------- kernel 5: per-class greedy NMS, one warp per (image,class) --------
#define WNMS_SMEM (8 * BK_CAP * (16 + 4 + 8 + 4))
extern __shared__ char wsm[];

__global__ void __launch_bounds__(256) warp_nms_kernel()
{
    int wid  = threadIdx.x >> 5;
    int lane = threadIdx.x & 31;
    int gw   = blockIdx.x * 8 + wid;
    if (gw >= BATCH * NCLS) return;
    int b = gw / NCLS, cls = gw - b * NCLS;

    float4* nbW = (float4*)wsm + wid * BK_CAP;
    float*  arW = (float*)(wsm + 8 * BK_CAP * 16) + wid * BK_CAP;
    u64*    skW = (u64*)(wsm + 8 * BK_CAP * 20) + wid * BK_CAP;
    int*    ssW = (int*)(wsm + 8 * BK_CAP * 28) + wid * BK_CAP;

    int n = min(g_bk_cnt[b][cls], BK_CAP);

    u64 key[8]; float4 nb[8]; float area[8];
    #pragma unroll
    for (int j = 0; j < 8; j++) {
        int idx = j * 32 + lane;
        key[j] = 0ull;
        nb[j]  = make_float4(0.f, 0.f, 0.f, 0.f);
        area[j] = 0.f;
        if (idx < n) {
            key[j]  = g_bk_key[b][cls][idx];
            nb[j]   = g_bk_nb[b][cls][idx];
            area[j] = g_bk_area[b][cls][idx];
            nbW[idx] = nb[j];
            arW[idx] = area[j];
        }
    }
    __syncwarp();

    int nsurv = 0;
    for (;;) {
        u64 bk = 0ull; int bj = 0;
        #pragma unroll
        for (int j = 0; j < 8; j++) if (key[j] > bk) { bk = key[j]; bj = j; }
        unsigned hi = (unsigned)(bk >> 32), lo = (unsigned)bk;
        unsigned mhi = __reduce_max_sync(0xffffffffu, hi);
        unsigned lo2 = (hi == mhi) ? lo : 0u;
        unsigned mlo = __reduce_max_sync(0xffffffffu, lo2);
        if ((mhi | mlo) == 0u) break;
        unsigned ball = __ballot_sync(0xffffffffu, (hi == mhi) && (lo == mlo));
        int wlane = __ffs(ball) - 1;
        int wj    = __shfl_sync(0xffffffffu, bj, wlane);
        int widx  = wj * 32 + wlane;
        if (lane == wlane) {
            skW[nsurv] = bk;
            ssW[nsurv] = cls * BK_CAP + widx;
        }
        nsurv++;
        float4 wb = nbW[widx];
        float  wa = arW[widx];
        #pragma unroll
        for (int j = 0; j < 8; j++) {
            if (key[j] != 0ull) {
                float yy1 = fmaxf(nb[j].x, wb.x);
                float xx1 = fmaxf(nb[j].y, wb.y);
                float yy2 = fminf(nb[j].z, wb.z);
                float xx2 = fminf(nb[j].w, wb.w);
                float ih = fmaxf(yy2 - yy1, 0.f);
                float iw = fmaxf(xx2 - xx1, 0.f);
                float inter = ih * iw;
                float iou = inter / (area[j] + wa - inter + 1e-8f);
                if (iou > 0.5f) key[j] = 0ull;
            }
        }
    }
    __syncwarp();

    int basep = 0;
    if (lane == 0) basep = atomicAdd(&g_surv_cnt[b], nsurv);
    basep = __shfl_sync(0xffffffffu, basep, 0);
    for (int s = lane; s < nsurv; s += 32) {
        int p = basep + s;
        if (p < KTOP) { g_surv_key[b][p] = skW[s]; g_surv_ref[b][p] = ssW[s]; }
    }
    if (lane == 0) g_bk_cnt[b][cls] = 0;
}

// ---------------- kernel 6: rank-based top-100 output (no sort) ---------------------
// keys distinct -> rank(i) = #{j: key_j > key_i}; rank<100 writes out[rank] directly.
__global__ void __launch_bounds__(1024) merge_kernel(const float* __restrict__ scales,
                                                     float* __restrict__ out)
{
    __shared__ u64 sK[KTOP];     // 40KB
    int b = blockIdx.x, tid = threadIdx.x;
    int m = min(g_surv_cnt[b], KTOP);

    // zero the 100 output rows first (rows >= m stay zero)
    if (tid < 100) {
        float* dstp = out + ((size_t)b * 100 + tid) * 6;
        #pragma unroll
        for (int c = 0; c < 6; c++) dstp[c] = 0.f;
    }

    for (int i = tid; i < m; i += 1024) sK[i] = g_surv_key[b][i];
    __syncthreads();

    u64 myk[5]; int rnk[5];
    #pragma unroll
    for (int s = 0; s < 5; s++) { myk[s] = 0ull; rnk[s] = 0x7FFFFFFF; }
    #pragma unroll
    for (int s = 0; s < 5; s++) {
        int i = s * 1024 + tid;
        if (i < m) { myk[s] = sK[i]; rnk[s] = 0; }
    }
    for (int j = 0; j < m; j++) {
        u64 kj = sK[j];                         // uniform j -> LDS broadcast
        #pragma unroll
        for (int s = 0; s < 5; s++)
            if (kj > myk[s]) rnk[s]++;
    }
    float sc = scales[b];
    #pragma unroll
    for (int s = 0; s < 5; s++) {
        int i = s * 1024 + tid;
        if (i < m && rnk[s] < 100) {
            int ref = g_surv_ref[b][i];
            int cls = ref / BK_CAP, pos = ref - cls * BK_CAP;
            const float* srcv = &g_bk_out6[b][cls][pos][0];
            float* dstp = out + ((size_t)b * 100 + rnk[s]) * 6;
            dstp[0] = srcv[0] * sc; dstp[1] = srcv[1] * sc;
            dstp[2] = srcv[2] * sc; dstp[3] = srcv[3] * sc;
            dstp[4] = srcv[4];      dstp[5] = srcv[5];
        }
    }
    if (tid == 0) g_surv_cnt[b] = 0;
}

// ---------------- launcher: identify inputs by element count ----------------
extern "C" void kernel_launch(void* const* d_in, const int* in_sizes, int n_in,
                              void* d_out, int out_size)
{
    const int clsSz[5] = {53084160, 13271040, 3317760, 829440, 207360};
    const int boxSz[5] = {2359296,  589824,   147456,  36864,  9216};
    const int anchSz = 196416, scaleSz = 16;

    const float* cls[5] = {0,0,0,0,0};
    const float* box[5] = {0,0,0,0,0};
    const float* anchors = 0;
    const float* scales  = 0;
    for (int i = 0; i < n_in; i++) {
        int s = in_sizes[i];
        const float* p = (const float*)d_in[i];
        if (s == anchSz)       anchors = p;
        else if (s == scaleSz) scales  = p;
        else {
            for (int l = 0; l < 5; l++) {
                if (s == clsSz[l]) cls[l] = p;
                if (s == boxSz[l]) box[l] = p;
            }
        }
    }
    float* out = (float*)d_out;

    cudaFuncSetAttribute(warp_nms_kernel,
                         cudaFuncAttributeMaxDynamicSharedMemorySize, WNMS_SMEM);

    collect_fused_kernel<<<NBLOCKS_TOTAL, 256>>>(cls[0], cls[1], cls[2], cls[3], cls[4]);
    bstar_kernel<<<BATCH, 1024>>>();
    scatter_kernel<<<BATCH * SC_BPI, 256>>>(box[0], box[1], box[2], box[3], box[4], anchors);
    eq_kernel<<<BATCH, 256>>>(box[0], box[1], box[2], box[3], box[4], anchors);
    warp_nms_kernel<<<(BATCH * NCLS + 7) / 8, 256, WNMS_SMEM>>>();
    merge_kernel<<<BATCH, 1024>>>(scales, out);
}

// round 15
// speedup vs baseline: 3.5354x; 3.5354x over previous
#include <cuda_runtime.h>
#include <stdint.h>
#include <math.h>

#define NCLS      90
#define KTOP      5000
#define BATCH     16
#define CAND_CAP  131072
#define THRESH    2.2f
#define NBINS     4096
#define NBINS_M   512
#define EQ_CAP    1024
#define BK_CAP    256
#define BLK_ELEMS 8192
#define NBLOCKS_TOTAL 8672
#define SC_BPI    64      // scatter blocks per image

typedef unsigned long long u64;

// ---------------- scratch (module-static device globals; no allocs) ----------------
__device__ uint2  g_cand[BATCH][CAND_CAP];
__device__ int    g_cand_cnt[BATCH];               // reset by eq_kernel
__device__ int    g_hist[BATCH][NBINS];            // filled by collect; reset by bstar
__device__ int    g_bstar[BATCH];
__device__ int    g_krem[BATCH];
__device__ u64    g_eq[BATCH][EQ_CAP];
__device__ int    g_eq_cnt[BATCH];                 // reset by eq_kernel
__device__ int    g_bk_cnt[BATCH][NCLS];           // reset by warp_nms
__device__ float4 g_bk_nb  [BATCH][NCLS][BK_CAP];
__device__ float  g_bk_area[BATCH][NCLS][BK_CAP];
__device__ u64    g_bk_key [BATCH][NCLS][BK_CAP];
__device__ float  g_bk_out6[BATCH][NCLS][BK_CAP][6];
__device__ int    g_surv_cnt[BATCH];               // reset by merge
__device__ u64    g_surv_key[BATCH][KTOP];
__device__ int    g_surv_ref[BATCH][KTOP];         // cls*BK_CAP + pos

__device__ __forceinline__ unsigned val2key(float v) {
    unsigned ub = __float_as_uint(v);
    return (ub & 0x80000000u) ? ~ub : (ub | 0x80000000u);
}
__device__ __forceinline__ float key2val(unsigned u) {
    unsigned bits = (u & 0x80000000u) ? (u & 0x7FFFFFFFu) : ~u;
    return __uint_as_float(bits);
}
__device__ __forceinline__ int val2bin(float v) {
    int bin = (int)((v - THRESH) * 1024.0f);
    return min(max(bin, 0), NBINS - 1);
}

// decode one candidate and push into its (image,class) bucket
__device__ __forceinline__ void decode_push(
    int b, unsigned keybits, unsigned flat,
    const float* __restrict__ bx0, const float* __restrict__ bx1,
    const float* __restrict__ bx2, const float* __restrict__ bx3,
    const float* __restrict__ bx4, const float* __restrict__ anchors)
{
    float v   = key2val(keybits);
    int cls   = (int)(flat % NCLS);
    int aIdx  = (int)(flat / NCLS);
    int off, W; const float* bp;
    if (aIdx < 36864)      { off = 0;     W = 64; bp = bx0; }
    else if (aIdx < 46080) { off = 36864; W = 32; bp = bx1; }
    else if (aIdx < 48384) { off = 46080; W = 16; bp = bx2; }
    else if (aIdx < 48960) { off = 48384; W = 8;  bp = bx3; }
    else                   { off = 48960; W = 4;  bp = bx4; }
    int rel  = aIdx - off;
    int a    = rel % 9, cell = rel / 9;
    int h    = cell / W, w = cell - h * W;
    int HW   = W * W;
    const float* bb = bp + ((size_t)b * 36 + (size_t)a * 4) * HW + h * W + w;
    float ty = bb[0], tx = bb[HW], th = bb[2 * HW], tw = bb[3 * HW];
    float a0 = anchors[aIdx * 4 + 0], a1 = anchors[aIdx * 4 + 1];
    float a2 = anchors[aIdx * 4 + 2], a3 = anchors[aIdx * 4 + 3];
    float ya = (a0 + a2) * 0.5f, xa = (a1 + a3) * 0.5f;
    float ha = a2 - a0, wa = a3 - a1;
    float hh = expf(th) * ha, ww2 = expf(tw) * wa;
    float yc = ty * ha + ya, xc = tx * wa + xa;
    float b0 = yc - hh * 0.5f, b1 = xc - ww2 * 0.5f;
    float b2 = yc + hh * 0.5f, b3 = xc + ww2 * 0.5f;
    float co = (float)cls * 10000.0f;
    float4 nb = make_float4(b0 + co, b1 + co, b2 + co, b3 + co);
    float ar  = (nb.z - nb.x) * (nb.w - nb.y);
    u64 key   = ((u64)keybits << 32) | (u64)(0xFFFFFFFFu - flat);
    float score = 1.0f / (1.0f + expf(-v));
    int p = atomicAdd(&g_bk_cnt[b][cls], 1);
    if (p < BK_CAP) {
        g_bk_nb[b][cls][p]   = nb;
        g_bk_area[b][cls][p] = ar;
        g_bk_key[b][cls][p]  = key;
        g_bk_out6[b][cls][p][0] = b0; g_bk_out6[b][cls][p][1] = b1;
        g_bk_out6[b][cls][p][2] = b2; g_bk_out6[b][cls][p][3] = b3;
        g_bk_out6[b][cls][p][4] = score;
        g_bk_out6[b][cls][p][5] = (float)(cls + 1);
    }
}

// ---------------- kernel 1: fused threshold-collect + histogram ---------------------
__global__ void __launch_bounds__(256) collect_fused_kernel(
    const float* __restrict__ c0, const float* __restrict__ c1,
    const float* __restrict__ c2, const float* __restrict__ c3,
    const float* __restrict__ c4)
{
    int bid = blockIdx.x;
    int lw, perImg, bpI, anchorOff, blk; const float* cp;
    if      (bid < 6480) { lw = 6; perImg = 3317760; bpI = 405; anchorOff = 0;     cp = c0; blk = bid; }
    else if (bid < 8112) { lw = 5; perImg = 829440;  bpI = 102; anchorOff = 36864; cp = c1; blk = bid - 6480; }
    else if (bid < 8528) { lw = 4; perImg = 207360;  bpI = 26;  anchorOff = 46080; cp = c2; blk = bid - 8112; }
    else if (bid < 8640) { lw = 3; perImg = 51840;   bpI = 7;   anchorOff = 48384; cp = c3; blk = bid - 8528; }
    else                 { lw = 2; perImg = 12960;   bpI = 2;   anchorOff = 48960; cp = c4; blk = bid - 8640; }

    int b     = blk / bpI;
    int chunk = blk - b * bpI;
    int base  = chunk * BLK_ELEMS + threadIdx.x * 4;

    __shared__ uint2 sc[512];
    __shared__ int scnt;
    __shared__ int sbase;
    if (threadIdx.x == 0) scnt = 0;
    __syncthreads();

    const float* img = cp + (size_t)b * perImg;

    float4 v[8];
    bool fullc = (chunk * BLK_ELEMS + BLK_ELEMS) <= perImg;
    if (fullc) {
        #pragma unroll
        for (int u = 0; u < 8; u++)
            v[u] = __ldcs(reinterpret_cast<const float4*>(img + base + u * 1024));
    } else {
        #pragma unroll
        for (int u = 0; u < 8; u++) {
            int g = base + u * 1024;
            if (g < perImg) v[u] = __ldcs(reinterpret_cast<const float4*>(img + g));
            else            v[u] = make_float4(-10.f, -10.f, -10.f, -10.f);
        }
    }

    unsigned hm = 0u;
    #pragma unroll
    for (int u = 0; u < 8; u++) {
        if (v[u].x > THRESH) hm |= (1u << (4 * u + 0));
        if (v[u].y > THRESH) hm |= (1u << (4 * u + 1));
        if (v[u].z > THRESH) hm |= (1u << (4 * u + 2));
        if (v[u].w > THRESH) hm |= (1u << (4 * u + 3));
    }

    int W = 1 << lw;
    while (hm) {
        int e = __ffs(hm) - 1;
        hm &= hm - 1;
        int gidx = base + ((e >> 2) << 10) + (e & 3);
        float val = __ldg(img + gidx);
        int w  = gidx & (W - 1);
        int t  = gidx >> lw;
        int h  = t & (W - 1);
        int ch = t >> lw;
        int a  = ch / NCLS;
        int c  = ch - a * NCLS;
        unsigned flat = (unsigned)((anchorOff + ((h << lw) + w) * 9 + a) * NCLS + c);
        atomicAdd(&g_hist[b][val2bin(val)], 1);        // fused histogram (spread bins)
        int p = atomicAdd(&scnt, 1);
        if (p < 512) sc[p] = make_uint2(val2key(val), flat);
    }
    __syncthreads();
    int cnt = min(scnt, 512);
    if (threadIdx.x == 0) sbase = atomicAdd(&g_cand_cnt[b], cnt);
    __syncthreads();
    if (threadIdx.x < cnt) {
        int p = sbase + threadIdx.x;
        if (p < CAND_CAP) g_cand[b][p] = sc[threadIdx.x];
    }
    for (int i = 256 + threadIdx.x; i < cnt; i += 256) {
        int p = sbase + i;
        if (p < CAND_CAP) g_cand[b][p] = sc[i];
    }
}

// ---------------- kernel 2: suffix-scan -> (bstar,krem); re-zero hist ---------------
__global__ void __launch_bounds__(1024) bstar_kernel()
{
    __shared__ int sA[NBINS];
    __shared__ int sB[NBINS];
    int b = blockIdx.x, tid = threadIdx.x;
    int n = min(g_cand_cnt[b], CAND_CAP);
    for (int i = tid; i < NBINS; i += 1024) {
        sA[i] = g_hist[b][i];
        g_hist[b][i] = 0;                       // reset for next replay
    }
    __syncthreads();
    int* src = sA; int* dst = sB;
    for (int off = 1; off < NBINS; off <<= 1) {
        for (int i = tid; i < NBINS; i += 1024)
            dst[i] = src[i] + ((i + off < NBINS) ? src[i + off] : 0);
        __syncthreads();
        int* tm = src; src = dst; dst = tm;
    }
    int K = (KTOP < n) ? KTOP : n;
    for (int i = tid; i < NBINS; i += 1024) {
        int inc = src[i];
        int exc = (i + 1 < NBINS) ? src[i + 1] : 0;
        if (inc >= K && exc < K) { g_bstar[b] = i; g_krem[b] = K - exc; }
    }
}

// ---------------- kernel 3: scatter + inline decode into class buckets --------------
__global__ void __launch_bounds__(256) scatter_kernel(
    const float* __restrict__ bx0, const float* __restrict__ bx1,
    const float* __restrict__ bx2, const float* __restrict__ bx3,
    const float* __restrict__ bx4, const float* __restrict__ anchors)
{
    int b   = blockIdx.x / SC_BPI;
    int sl  = blockIdx.x - b * SC_BPI;
    int n   = min(g_cand_cnt[b], CAND_CAP);
    int per = (n + SC_BPI - 1) / SC_BPI;
    int lo  = sl * per, hi = min(lo + per, n);
    int bstar = g_bstar[b];
    for (int i = lo + threadIdx.x; i < hi; i += 256) {
        uint2 e = g_cand[b][i];
        float v = key2val(e.x);
        int bin = val2bin(v);
        if (bin > bstar) {
            decode_push(b, e.x, e.y, bx0, bx1, bx2, bx3, bx4, anchors);
        } else if (bin == bstar) {
            int p = atomicAdd(&g_eq_cnt[b], 1);
            if (p < EQ_CAP)
                g_eq[b][p] = ((u64)e.x << 32) | (u64)(0xFFFFFFFFu - e.y);
        }
    }
}

// ---------------- kernel 4: boundary bin: sort, take exactly krem, decode -----------
__global__ void __launch_bounds__(256) eq_kernel(
    const float* __restrict__ bx0, const float* __restrict__ bx1,
    const float* __restrict__ bx2, const float* __restrict__ bx3,
    const float* __restrict__ bx4, const float* __restrict__ anchors)
{
    __shared__ u64 eqS[EQ_CAP];
    int b = blockIdx.x, tid = threadIdx.x;
    int eq = min(g_eq_cnt[b], EQ_CAP);
    int krem = g_krem[b];
    int P = 1; while (P < eq) P <<= 1;
    if (P < 1) P = 1;
    for (int i = tid; i < P; i += 256) eqS[i] = (i < eq) ? g_eq[b][i] : 0ull;
    __syncthreads();
    for (int ksz = 2; ksz <= P; ksz <<= 1) {
        for (int j = ksz >> 1; j > 0; j >>= 1) {
            for (int i = tid; i < P; i += 256) {
                int ixj = i ^ j;
                if (ixj > i) {
                    u64 a = eqS[i], c = eqS[ixj];
                    bool descSeg = ((i & ksz) == 0);
                    if (descSeg ? (a < c) : (a > c)) { eqS[i] = c; eqS[ixj] = a; }
                }
            }
            __syncthreads();
        }
    }
    if (krem > eq) krem = eq;
    for (int i = tid; i < krem; i += 256) {
        u64 a = eqS[i];
        decode_push(b, (unsigned)(a >> 32), 0xFFFFFFFFu - (unsigned)(a & 0xFFFFFFFFull),
                    bx0, bx1, bx2, bx3, bx4, anchors);
    }
    if (tid == 0) { g_eq_cnt[b] = 0; g_cand_cnt[b] = 0; }
}

// ---------------- kernel 5: per-class greedy NMS, one warp per (image,class) --------
#define WNMS_SMEM (8 * BK_CAP * (16 + 4 + 8 + 4))
extern __shared__ char wsm[];

__global__ void __launch_bounds__(256) warp_nms_kernel()
{
    int wid  = threadIdx.x >> 5;
    int lane = threadIdx.x & 31;
    int gw   = blockIdx.x * 8 + wid;
    if (gw >= BATCH * NCLS) return;
    int b = gw / NCLS, cls = gw - b * NCLS;

    float4* nbW = (float4*)wsm + wid * BK_CAP;
    float*  arW = (float*)(wsm + 8 * BK_CAP * 16) + wid * BK_CAP;
    u64*    skW = (u64*)(wsm + 8 * BK_CAP * 20) + wid * BK_CAP;
    int*    ssW = (int*)(wsm + 8 * BK_CAP * 28) + wid * BK_CAP;

    int n = min(g_bk_cnt[b][cls], BK_CAP);

    u64 key[8]; float4 nb[8]; float area[8];
    #pragma unroll
    for (int j = 0; j < 8; j++) {
        int idx = j * 32 + lane;
        key[j] = 0ull;
        nb[j]  = make_float4(0.f, 0.f, 0.f, 0.f);
        area[j] = 0.f;
        if (idx < n) {
            key[j]  = g_bk_key[b][cls][idx];
            nb[j]   = g_bk_nb[b][cls][idx];
            area[j] = g_bk_area[b][cls][idx];
            nbW[idx] = nb[j];
            arW[idx] = area[j];
        }
    }
    __syncwarp();

    int nsurv = 0;
    for (;;) {
        u64 bk = 0ull; int bj = 0;
        #pragma unroll
        for (int j = 0; j < 8; j++) if (key[j] > bk) { bk = key[j]; bj = j; }
        unsigned hi = (unsigned)(bk >> 32), lo = (unsigned)bk;
        unsigned mhi = __reduce_max_sync(0xffffffffu, hi);
        unsigned lo2 = (hi == mhi) ? lo : 0u;
        unsigned mlo = __reduce_max_sync(0xffffffffu, lo2);
        if ((mhi | mlo) == 0u) break;
        unsigned ball = __ballot_sync(0xffffffffu, (hi == mhi) && (lo == mlo));
        int wlane = __ffs(ball) - 1;
        int wj    = __shfl_sync(0xffffffffu, bj, wlane);
        int widx  = wj * 32 + wlane;
        if (lane == wlane) {
            skW[nsurv] = bk;
            ssW[nsurv] = cls * BK_CAP + widx;
        }
        nsurv++;
        float4 wb = nbW[widx];
        float  wa = arW[widx];
        #pragma unroll
        for (int j = 0; j < 8; j++) {
            if (key[j] != 0ull) {
                float yy1 = fmaxf(nb[j].x, wb.x);
                float xx1 = fmaxf(nb[j].y, wb.y);
                float yy2 = fminf(nb[j].z, wb.z);
                float xx2 = fminf(nb[j].w, wb.w);
                float ih = fmaxf(yy2 - yy1, 0.f);
                float iw = fmaxf(xx2 - xx1, 0.f);
                float inter = ih * iw;
                float iou = inter / (area[j] + wa - inter + 1e-8f);
                if (iou > 0.5f) key[j] = 0ull;
            }
        }
    }
    __syncwarp();

    int basep = 0;
    if (lane == 0) basep = atomicAdd(&g_surv_cnt[b], nsurv);
    basep = __shfl_sync(0xffffffffu, basep, 0);
    for (int s = lane; s < nsurv; s += 32) {
        int p = basep + s;
        if (p < KTOP) { g_surv_key[b][p] = skW[s]; g_surv_ref[b][p] = ssW[s]; }
    }
    if (lane == 0) g_bk_cnt[b][cls] = 0;
}

// ---------------- kernel 6: exact top-100 merge (512-bin cut + compact + bitonic) ---
__global__ void __launch_bounds__(1024) merge_kernel(const float* __restrict__ scales,
                                                     float* __restrict__ out)
{
    __shared__ int histA[NBINS_M];
    __shared__ int histB[NBINS_M];
    __shared__ u64 sKeys[1024];
    __shared__ int sRef[1024];
    __shared__ int s_bstar, s_cnt;

    int b = blockIdx.x, tid = threadIdx.x;
    int m = min(g_surv_cnt[b], KTOP);

    if (tid < NBINS_M) histA[tid] = 0;
    if (tid == 0) { s_cnt = 0; s_bstar = 0; }
    __syncthreads();

    for (int i = tid; i < m; i += 1024) {
        float v = key2val((unsigned)(g_surv_key[b][i] >> 32));
        int bin = (int)((v - THRESH) * 128.0f);
        bin = min(max(bin, 0), NBINS_M - 1);
        atomicAdd(&histA[bin], 1);
    }
    __syncthreads();

    int* src = histA; int* dst = histB;
    for (int off = 1; off < NBINS_M; off <<= 1) {
        if (tid < NBINS_M)
            dst[tid] = src[tid] + ((tid + off < NBINS_M) ? src[tid + off] : 0);
        __syncthreads();
        int* tm = src; src = dst; dst = tm;
    }
    int K = min(100, m);
    if (K > 0 && tid < NBINS_M) {
        int inc = src[tid];
        int exc = (tid + 1 < NBINS_M) ? src[tid + 1] : 0;
        if (inc >= K && exc < K) s_bstar = tid;
    }
    __syncthreads();
    int bstar = s_bstar;

    for (int i = tid; i < m; i += 1024) {
        u64 key = g_surv_key[b][i];
        float v = key2val((unsigned)(key >> 32));
        int bin = (int)((v - THRESH) * 128.0f);
        bin = min(max(bin, 0), NBINS_M - 1);
        if (bin >= bstar) {
            int p = atomicAdd(&s_cnt, 1);
            if (p < 1024) { sKeys[p] = key; sRef[p] = g_surv_ref[b][i]; }
        }
    }
    __syncthreads();
    int C = min(s_cnt, 1024);
    for (int i = C + tid; i < 1024; i += 1024) { sKeys[i] = 0ull; sRef[i] = 0; }
    __syncthreads();

    for (int ksz = 2; ksz <= 1024; ksz <<= 1) {
        for (int j = ksz >> 1; j > 0; j >>= 1) {
            int i = tid, ixj = tid ^ j;
            if (ixj > i) {
                u64 a = sKeys[i], c = sKeys[ixj];
                bool descSeg = ((i & ksz) == 0);
                if (descSeg ? (a < c) : (a > c)) {
                    sKeys[i] = c; sKeys[ixj] = a;
                    int t = sRef[i]; sRef[i] = sRef[ixj]; sRef[ixj] = t;
                }
            }
            __syncthreads();
        }
    }

    if (tid < 100) {
        float o[6] = {0.f, 0.f, 0.f, 0.f, 0.f, 0.f};
        if (sKeys[tid] != 0ull) {
            int ref = sRef[tid];
            int cls = ref / BK_CAP, pos = ref - cls * BK_CAP;
            float sc = scales[b];
            const float* srcv = &g_bk_out6[b][cls][pos][0];
            o[0] = srcv[0] * sc; o[1] = srcv[1] * sc;
            o[2] = srcv[2] * sc; o[3] = srcv[3] * sc;
            o[4] = srcv[4];      o[5] = srcv[5];
        }
        float* dstp = out + ((size_t)b * 100 + tid) * 6;
        #pragma unroll
        for (int c = 0; c < 6; c++) dstp[c] = o[c];
    }
    if (tid == 0) g_surv_cnt[b] = 0;
}

// ---------------- launcher: identify inputs by element count ----------------
extern "C" void kernel_launch(void* const* d_in, const int* in_sizes, int n_in,
                              void* d_out, int out_size)
{
    const int clsSz[5] = {53084160, 13271040, 3317760, 829440, 207360};
    const int boxSz[5] = {2359296,  589824,   147456,  36864,  9216};
    const int anchSz = 196416, scaleSz = 16;

    const float* cls[5] = {0,0,0,0,0};
    const float* box[5] = {0,0,0,0,0};
    const float* anchors = 0;
    const float* scales  = 0;
    for (int i = 0; i < n_in; i++) {
        int s = in_sizes[i];
        const float* p = (const float*)d_in[i];
        if (s == anchSz)       anchors = p;
        else if (s == scaleSz) scales  = p;
        else {
            for (int l = 0; l < 5; l++) {
                if (s == clsSz[l]) cls[l] = p;
                if (s == boxSz[l]) box[l] = p;
            }
        }
    }
    float* out = (float*)d_out;

    cudaFuncSetAttribute(warp_nms_kernel,
                         cudaFuncAttributeMaxDynamicSharedMemorySize, WNMS_SMEM);

    collect_fused_kernel<<<NBLOCKS_TOTAL, 256>>>(cls[0], cls[1], cls[2], cls[3], cls[4]);
    bstar_kernel<<<BATCH, 1024>>>();
    scatter_kernel<<<BATCH * SC_BPI, 256>>>(box[0], box[1], box[2], box[3], box[4], anchors);
    eq_kernel<<<BATCH, 256>>>(box[0], box[1], box[2], box[3], box[4], anchors);
    warp_nms_kernel<<<(BATCH * NCLS + 7) / 8, 256, WNMS_SMEM>>>();
    merge_kernel<<<BATCH, 1024>>>(scales, out);
}